// round 15
// baseline (speedup 1.0000x reference)
#include <cuda_runtime.h>
#include <cuda_fp16.h>
#include <cstdint>

// Problem constants
#define B_   4
#define N_   4096
#define D_   1024
#define H_   16
#define DH_  64
#define L_   64
#define NCH_ (N_ / L_)           // 64
#define M_   (B_ * N_)           // 16384 tokens

// Scratch (__device__ globals; no allocation allowed)
__device__ float g_carry[B_ * NCH_ * D_];
__device__ unsigned int g_bar;               // monotonic barrier ticket counter
__device__ __half g_a[M_ * D_];              // fp16 activations (post-norm)
__device__ __half g_w[D_ * D_];              // o_w fp16

__device__ __forceinline__ float pow_int(float base, int e) {
    float p = 1.0f, b = base;
    while (e) { if (e & 1) p *= b; b *= b; e >>= 1; }
    return p;
}

__device__ __forceinline__ uint32_t smem_u32(const void* p) {
    uint32_t a;
    asm("{ .reg .u64 t; cvta.to.shared.u64 t, %1; cvt.u32.u64 %0, t; }" : "=r"(a) : "l"(p));
    return a;
}

#define CP_ASYNC16(dst, src) \
    asm volatile("cp.async.cg.shared.global [%0], [%1], 16;" :: "r"(dst), "l"(src) : "memory")
#define CP_COMMIT() asm volatile("cp.async.commit_group;" ::: "memory")
#define CP_WAIT1()  asm volatile("cp.async.wait_group 1;" ::: "memory")

#define LDSM4(r0, r1, r2, r3, addr) \
    asm volatile("ldmatrix.sync.aligned.m8n8.x4.shared.b16 {%0,%1,%2,%3}, [%4];" \
                 : "=r"(r0), "=r"(r1), "=r"(r2), "=r"(r3) : "r"(addr))

#define MMA_F16(d, a, b) \
    asm volatile("mma.sync.aligned.m16n8k16.row.col.f32.f16.f16.f32 " \
                 "{%0,%1,%2,%3}, {%4,%5,%6,%7}, {%8,%9}, {%0,%1,%2,%3};" \
                 : "+f"((d)[0]), "+f"((d)[1]), "+f"((d)[2]), "+f"((d)[3]) \
                 : "r"((a)[0]), "r"((a)[1]), "r"((a)[2]), "r"((a)[3]), \
                   "r"((b)[0]), "r"((b)[1]))

// ============================ fused scan (single kernel) ============================
// 256 blocks x 1024 threads, one block per (b, chunk). All blocks co-resident
// (occ=2, 296 slots >= 256), so a grid barrier is safe. Monotonic ticket
// barrier is graph-replay safe (no counter reset needed).
#define SNORM_SMEM (16 * 1024 * 4 + 128)

__global__ __launch_bounds__(1024, 2) void k_scan_fused(
        const float* __restrict__ x, const float* __restrict__ norm_weight,
        const float* __restrict__ q, const float* __restrict__ k,
        const float* __restrict__ log_decay, const float* __restrict__ w) {
    extern __shared__ float sv[];                    // [16][1024]
    float* s_rstd = sv + 16 * 1024;                  // [16]
    int blk = blockIdx.x;
    int b = blk / NCH_;
    int c = blk % NCH_;
    int d = threadIdx.x;
    int lane = d & 31, wrp = d >> 5;
    int h = d >> 6;

    // --- per-thread head constants (no cross-block dependency) ---
    float lam = 1.0f / (1.0f + expf(-log_decay[h]));
    float ch = 0.0f;
    {
        const float* qh = q + h * DH_;
        const float* kh = k + h * DH_;
        #pragma unroll 16
        for (int j = 0; j < DH_; j++) ch = fmaf(qh[j], kh[j], ch);
    }
    float nw  = norm_weight[d];
    float lamL = pow_int(lam, L_);

    // --- weight fp16 conversion: exactly one float4 per thread ---
    {
        size_t off = ((size_t)blk * 1024 + d) * 4;
        float4 v = *(const float4*)&w[off];
        __half2 p0 = __floats2half2_rn(v.x, v.y);
        __half2 p1 = __floats2half2_rn(v.z, v.w);
        *(__half2*)&g_w[off]     = p0;
        *(__half2*)&g_w[off + 2] = p1;
    }

    // --- phase 1: local chunk carry ---
    size_t xbase = (size_t)(b * N_ + c * L_) * D_ + d;
    {
        float s = 0.0f;
        #pragma unroll 8
        for (int t = 0; t < L_; t++) s = fmaf(lam, s, x[xbase + (size_t)t * D_]);
        g_carry[(b * NCH_ + c) * D_ + d] = s;
    }

    // --- grid barrier (monotonic ticket; graph-replay safe) ---
    __syncthreads();
    if (d == 0) {
        __threadfence();
        unsigned int ticket = atomicAdd(&g_bar, 1u);
        unsigned int target = ((ticket >> 8) + 1u) << 8;   // 256 blocks/launch
        unsigned int cur;
        do {
            asm volatile("ld.acquire.gpu.global.u32 %0, [%1];" : "=r"(cur) : "l"(&g_bar));
        } while (cur < target);
    }
    __syncthreads();

    // --- phase 2: fold prefix of carries (coalesced, L2-resident) ---
    float P = 0.0f;
    {
        int base = b * NCH_ * D_ + d;
        int j = 0;
        for (; j + 8 <= c; j += 8) {
            float v[8];
            #pragma unroll
            for (int u = 0; u < 8; u++) v[u] = g_carry[base + (j + u) * D_];
            #pragma unroll
            for (int u = 0; u < 8; u++) P = fmaf(lamL, P, v[u]);
        }
        for (; j < c; j++) P = fmaf(lamL, P, g_carry[base + j * D_]);
    }

    // --- phase 3: re-scan chunk (x L1/L2-warm) + RMSNorm + fp16 store ---
    float s = P;
    #pragma unroll
    for (int quar = 0; quar < 4; quar++) {
        #pragma unroll 8
        for (int t = 0; t < 16; t++) {
            s = fmaf(lam, s, x[xbase + (size_t)(quar * 16 + t) * D_]);
            sv[t * 1024 + d] = s * ch;
        }
        __syncthreads();
        if (wrp < 16) {
            float ss = 0.0f;
            const float* row = sv + wrp * 1024;
            #pragma unroll
            for (int j = 0; j < 32; j++) {
                float vv = row[lane + 32 * j];
                ss = fmaf(vv, vv, ss);
            }
            #pragma unroll
            for (int o = 16; o > 0; o >>= 1) ss += __shfl_xor_sync(0xFFFFFFFFu, ss, o);
            if (lane == 0) s_rstd[wrp] = rsqrtf(ss * (1.0f / (float)D_) + 1e-6f);
        }
        __syncthreads();
        int tok0 = (b * N_ + c * L_ + quar * 16);
        #pragma unroll 4
        for (int t = 0; t < 16; t++) {
            float a = sv[t * 1024 + d] * s_rstd[t] * nw;
            float a1 = __shfl_down_sync(0xFFFFFFFFu, a, 1);
            if (!(d & 1)) {
                __half2 p = __floats2half2_rn(a, a1);
                *(__half2*)&g_a[(size_t)(tok0 + t) * D_ + d] = p;
            }
        }
        __syncthreads();
    }
}

// ============================ HMMA GEMM (known-good config) ============================
// C = A * W^T (fp16 in, fp32 accum). CTA 128x128, BK=64, 8 warps (4m x 2n),
// warp 32x64. STG=3 x 32KB -> 96KB/CTA -> occ=2. One barrier per stage.
#define GM 128
#define GN 128
#define KS 64
#define STG 3
#define NITER 16
#define TILE_B 16384
#define STAGE_BYTES (2 * TILE_B)                // A + W = 32KB
#define SMEM_GEMM_TOTAL (STG * STAGE_BYTES)     // 96KB

#define SMEM_SWZ(off) ((off) ^ (((off) >> 3) & 0x70))

__device__ __forceinline__ void load_stage(uint32_t smem_base, int round, int buf,
                                           int bm, int bn, int tid) {
    int k0 = round * KS;
    uint32_t st = smem_base + buf * STAGE_BYTES;
    #pragma unroll
    for (int i = 0; i < 8; i++) {
        int idx = i * 256 + tid;               // [0, 2048)
        int tile = idx >> 10;                  // 0:A 1:W
        int c = idx & 1023;
        int r = c >> 3, kc = c & 7;
        const __half* src = tile ? g_w : g_a;
        int row = (tile ? bn : bm) + r;
        const __half* g = src + (size_t)row * D_ + k0 + kc * 8;
        CP_ASYNC16(st + tile * TILE_B + SMEM_SWZ(r * 128 + kc * 16), g);
    }
}

__global__ __launch_bounds__(256, 2) void k_gemm_mma(float* __restrict__ C) {
    extern __shared__ char smem[];
    uint32_t sb = smem_u32(smem);
    const int tid  = threadIdx.x;
    const int wid  = tid >> 5;
    const int lane = tid & 31;
    const int wm   = wid >> 1;
    const int wn   = wid & 1;
    const int bm   = blockIdx.y * GM;
    const int bn   = blockIdx.x * GN;

    const int t7 = lane & 7;
    const int q  = lane >> 3;
    const int a_row = wm * 32 + (q & 1) * 8 + t7;
    const int a_cq  = q >> 1;
    const int b_row = wn * 64 + (q >> 1) * 8 + t7;
    const int b_cq  = q & 1;

    float acc[2][8][4];
    #pragma unroll
    for (int im = 0; im < 2; im++)
        #pragma unroll
        for (int j = 0; j < 8; j++)
            #pragma unroll
            for (int e = 0; e < 4; e++) acc[im][j][e] = 0.0f;

    load_stage(sb, 0, 0, bm, bn, tid); CP_COMMIT();
    load_stage(sb, 1, 1, bm, bn, tid); CP_COMMIT();

    int buf = 0;
    int lbuf = 2;
    for (int i = 0; i < NITER; i++) {
        CP_WAIT1();
        __syncthreads();

        int j = i + 2;
        if (j < NITER) load_stage(sb, j, lbuf, bm, bn, tid);
        CP_COMMIT();

        uint32_t st = sb + buf * STAGE_BYTES;
        #pragma unroll
        for (int ks = 0; ks < 4; ks++) {
            uint32_t af[2][4];
            #pragma unroll
            for (int im = 0; im < 2; im++) {
                uint32_t ro = (a_row + im * 16) * 128 + (((ks * 2 + a_cq) ^ t7) << 4);
                LDSM4(af[im][0], af[im][1], af[im][2], af[im][3], st + ro);
            }
            uint32_t bf[8][2];
            #pragma unroll
            for (int jj = 0; jj < 4; jj++) {
                uint32_t ro = (b_row + jj * 16) * 128 + (((ks * 2 + b_cq) ^ t7) << 4);
                LDSM4(bf[2*jj][0], bf[2*jj][1], bf[2*jj+1][0], bf[2*jj+1][1],
                      st + TILE_B + ro);
            }
            #pragma unroll
            for (int im = 0; im < 2; im++)
                #pragma unroll
                for (int jt = 0; jt < 8; jt++)
                    MMA_F16(acc[im][jt], af[im], bf[jt]);
        }

        buf  = (buf == STG - 1) ? 0 : buf + 1;
        lbuf = (lbuf == STG - 1) ? 0 : lbuf + 1;
    }

    #pragma unroll
    for (int im = 0; im < 2; im++) {
        int r0 = bm + wm * 32 + im * 16 + (lane >> 2);
        #pragma unroll
        for (int jt = 0; jt < 8; jt++) {
            int c = bn + wn * 64 + jt * 8 + (lane & 3) * 2;
            *(float2*)&C[(size_t)r0 * D_ + c]       = make_float2(acc[im][jt][0], acc[im][jt][1]);
            *(float2*)&C[(size_t)(r0 + 8) * D_ + c] = make_float2(acc[im][jt][2], acc[im][jt][3]);
        }
    }
}

// ============================ launch ============================
extern "C" void kernel_launch(void* const* d_in, const int* in_sizes, int n_in,
                              void* d_out, int out_size) {
    const float* x           = (const float*)d_in[0];
    const float* q           = (const float*)d_in[1];
    const float* k           = (const float*)d_in[2];
    const float* log_decay   = (const float*)d_in[3];
    const float* norm_weight = (const float*)d_in[4];
    const float* o_w         = (const float*)d_in[5];
    float* out = (float*)d_out;

    cudaFuncSetAttribute(k_scan_fused, cudaFuncAttributeMaxDynamicSharedMemorySize, SNORM_SMEM);
    k_scan_fused<<<B_ * NCH_, 1024, SNORM_SMEM>>>(x, norm_weight, q, k, log_decay, o_w);

    cudaFuncSetAttribute(k_gemm_mma, cudaFuncAttributeMaxDynamicSharedMemorySize,
                         SMEM_GEMM_TOTAL);
    dim3 grid(D_ / GN, M_ / GM);
    k_gemm_mma<<<grid, 256, SMEM_GEMM_TOTAL>>>(out);
}

// round 16
// speedup vs baseline: 1.0029x; 1.0029x over previous
#include <cuda_runtime.h>
#include <cuda_fp16.h>
#include <cstdint>

// Problem constants
#define B_   4
#define N_   4096
#define D_   1024
#define H_   16
#define DH_  64
#define L_   64
#define NCH_ (N_ / L_)           // 64
#define M_   (B_ * N_)           // 16384 tokens

// Scratch (__device__ globals; no allocation allowed)
__device__ float g_carry[B_ * NCH_ * D_];
__device__ unsigned int g_bar;               // monotonic barrier ticket counter
__device__ __half g_a[M_ * D_];              // fp16 activations (post-norm)
__device__ __half g_w[D_ * D_];              // o_w fp16

__device__ __forceinline__ float pow_int(float base, int e) {
    float p = 1.0f, b = base;
    while (e) { if (e & 1) p *= b; b *= b; e >>= 1; }
    return p;
}

__device__ __forceinline__ uint32_t smem_u32(const void* p) {
    uint32_t a;
    asm("{ .reg .u64 t; cvta.to.shared.u64 t, %1; cvt.u32.u64 %0, t; }" : "=r"(a) : "l"(p));
    return a;
}

#define CP_ASYNC16(dst, src) \
    asm volatile("cp.async.cg.shared.global [%0], [%1], 16;" :: "r"(dst), "l"(src) : "memory")
#define CP_COMMIT() asm volatile("cp.async.commit_group;" ::: "memory")
#define CP_WAIT1()  asm volatile("cp.async.wait_group 1;" ::: "memory")

#define LDSM4(r0, r1, r2, r3, addr) \
    asm volatile("ldmatrix.sync.aligned.m8n8.x4.shared.b16 {%0,%1,%2,%3}, [%4];" \
                 : "=r"(r0), "=r"(r1), "=r"(r2), "=r"(r3) : "r"(addr))

#define MMA_F16(d, a, b) \
    asm volatile("mma.sync.aligned.m16n8k16.row.col.f32.f16.f16.f32 " \
                 "{%0,%1,%2,%3}, {%4,%5,%6,%7}, {%8,%9}, {%0,%1,%2,%3};" \
                 : "+f"((d)[0]), "+f"((d)[1]), "+f"((d)[2]), "+f"((d)[3]) \
                 : "r"((a)[0]), "r"((a)[1]), "r"((a)[2]), "r"((a)[3]), \
                   "r"((b)[0]), "r"((b)[1]))

// ============================ fused scan (single kernel) ============================
// 256 blocks x 1024 threads, one block per (b, chunk). All blocks co-resident
// (occ=2, 296 slots >= 256), so a grid barrier is safe. Monotonic ticket
// barrier is graph-replay safe (no counter reset needed).
#define SNORM_SMEM (16 * 1024 * 4 + 128)

__global__ __launch_bounds__(1024, 2) void k_scan_fused(
        const float* __restrict__ x, const float* __restrict__ norm_weight,
        const float* __restrict__ q, const float* __restrict__ k,
        const float* __restrict__ log_decay, const float* __restrict__ w) {
    extern __shared__ float sv[];                    // [16][1024]
    float* s_rstd = sv + 16 * 1024;                  // [16]
    int blk = blockIdx.x;
    int b = blk / NCH_;
    int c = blk % NCH_;
    int d = threadIdx.x;
    int lane = d & 31, wrp = d >> 5;
    int h = d >> 6;

    // --- per-thread head constants (no cross-block dependency) ---
    float lam = 1.0f / (1.0f + expf(-log_decay[h]));
    float ch = 0.0f;
    {
        const float* qh = q + h * DH_;
        const float* kh = k + h * DH_;
        #pragma unroll 16
        for (int j = 0; j < DH_; j++) ch = fmaf(qh[j], kh[j], ch);
    }
    float nw  = norm_weight[d];
    float lamL = pow_int(lam, L_);

    // --- weight fp16 conversion: exactly one float4 per thread ---
    {
        size_t off = ((size_t)blk * 1024 + d) * 4;
        float4 v = *(const float4*)&w[off];
        __half2 p0 = __floats2half2_rn(v.x, v.y);
        __half2 p1 = __floats2half2_rn(v.z, v.w);
        *(__half2*)&g_w[off]     = p0;
        *(__half2*)&g_w[off + 2] = p1;
    }

    // --- phase 1: local chunk carry ---
    size_t xbase = (size_t)(b * N_ + c * L_) * D_ + d;
    {
        float s = 0.0f;
        #pragma unroll 8
        for (int t = 0; t < L_; t++) s = fmaf(lam, s, x[xbase + (size_t)t * D_]);
        g_carry[(b * NCH_ + c) * D_ + d] = s;
    }

    // --- grid barrier (monotonic ticket; graph-replay safe) ---
    __syncthreads();
    if (d == 0) {
        __threadfence();
        unsigned int ticket = atomicAdd(&g_bar, 1u);
        unsigned int target = ((ticket >> 8) + 1u) << 8;   // 256 blocks/launch
        unsigned int cur;
        do {
            asm volatile("ld.acquire.gpu.global.u32 %0, [%1];" : "=r"(cur) : "l"(&g_bar));
        } while (cur < target);
    }
    __syncthreads();

    // --- phase 2: fold prefix of carries (coalesced, L2-resident) ---
    float P = 0.0f;
    {
        int base = b * NCH_ * D_ + d;
        int j = 0;
        for (; j + 8 <= c; j += 8) {
            float v[8];
            #pragma unroll
            for (int u = 0; u < 8; u++) v[u] = g_carry[base + (j + u) * D_];
            #pragma unroll
            for (int u = 0; u < 8; u++) P = fmaf(lamL, P, v[u]);
        }
        for (; j < c; j++) P = fmaf(lamL, P, g_carry[base + j * D_]);
    }

    // --- phase 3: re-scan chunk (x L1/L2-warm) + RMSNorm + fp16 store ---
    float s = P;
    #pragma unroll
    for (int quar = 0; quar < 4; quar++) {
        #pragma unroll 8
        for (int t = 0; t < 16; t++) {
            s = fmaf(lam, s, x[xbase + (size_t)(quar * 16 + t) * D_]);
            sv[t * 1024 + d] = s * ch;
        }
        __syncthreads();
        if (wrp < 16) {
            float ss = 0.0f;
            const float* row = sv + wrp * 1024;
            #pragma unroll
            for (int j = 0; j < 32; j++) {
                float vv = row[lane + 32 * j];
                ss = fmaf(vv, vv, ss);
            }
            #pragma unroll
            for (int o = 16; o > 0; o >>= 1) ss += __shfl_xor_sync(0xFFFFFFFFu, ss, o);
            if (lane == 0) s_rstd[wrp] = rsqrtf(ss * (1.0f / (float)D_) + 1e-6f);
        }
        __syncthreads();
        int tok0 = (b * N_ + c * L_ + quar * 16);
        #pragma unroll 4
        for (int t = 0; t < 16; t++) {
            float a = sv[t * 1024 + d] * s_rstd[t] * nw;
            float a1 = __shfl_down_sync(0xFFFFFFFFu, a, 1);
            if (!(d & 1)) {
                __half2 p = __floats2half2_rn(a, a1);
                *(__half2*)&g_a[(size_t)(tok0 + t) * D_ + d] = p;
            }
        }
        __syncthreads();
    }
}

// ============================ HMMA GEMM (known-good config) ============================
// C = A * W^T (fp16 in, fp32 accum). CTA 128x128, BK=64, 8 warps (4m x 2n),
// warp 32x64. STG=3 x 32KB -> 96KB/CTA -> occ=2. One barrier per stage.
#define GM 128
#define GN 128
#define KS 64
#define STG 3
#define NITER 16
#define TILE_B 16384
#define STAGE_BYTES (2 * TILE_B)                // A + W = 32KB
#define SMEM_GEMM_TOTAL (STG * STAGE_BYTES)     // 96KB

#define SMEM_SWZ(off) ((off) ^ (((off) >> 3) & 0x70))

__device__ __forceinline__ void load_stage(uint32_t smem_base, int round, int buf,
                                           int bm, int bn, int tid) {
    int k0 = round * KS;
    uint32_t st = smem_base + buf * STAGE_BYTES;
    #pragma unroll
    for (int i = 0; i < 8; i++) {
        int idx = i * 256 + tid;               // [0, 2048)
        int tile = idx >> 10;                  // 0:A 1:W
        int c = idx & 1023;
        int r = c >> 3, kc = c & 7;
        const __half* src = tile ? g_w : g_a;
        int row = (tile ? bn : bm) + r;
        const __half* g = src + (size_t)row * D_ + k0 + kc * 8;
        CP_ASYNC16(st + tile * TILE_B + SMEM_SWZ(r * 128 + kc * 16), g);
    }
}

__global__ __launch_bounds__(256, 2) void k_gemm_mma(float* __restrict__ C) {
    extern __shared__ char smem[];
    uint32_t sb = smem_u32(smem);
    const int tid  = threadIdx.x;
    const int wid  = tid >> 5;
    const int lane = tid & 31;
    const int wm   = wid >> 1;
    const int wn   = wid & 1;
    const int bm   = blockIdx.y * GM;
    const int bn   = blockIdx.x * GN;

    const int t7 = lane & 7;
    const int q  = lane >> 3;
    const int a_row = wm * 32 + (q & 1) * 8 + t7;
    const int a_cq  = q >> 1;
    const int b_row = wn * 64 + (q >> 1) * 8 + t7;
    const int b_cq  = q & 1;

    float acc[2][8][4];
    #pragma unroll
    for (int im = 0; im < 2; im++)
        #pragma unroll
        for (int j = 0; j < 8; j++)
            #pragma unroll
            for (int e = 0; e < 4; e++) acc[im][j][e] = 0.0f;

    load_stage(sb, 0, 0, bm, bn, tid); CP_COMMIT();
    load_stage(sb, 1, 1, bm, bn, tid); CP_COMMIT();

    int buf = 0;
    int lbuf = 2;
    for (int i = 0; i < NITER; i++) {
        CP_WAIT1();
        __syncthreads();

        int j = i + 2;
        if (j < NITER) load_stage(sb, j, lbuf, bm, bn, tid);
        CP_COMMIT();

        uint32_t st = sb + buf * STAGE_BYTES;
        #pragma unroll
        for (int ks = 0; ks < 4; ks++) {
            uint32_t af[2][4];
            #pragma unroll
            for (int im = 0; im < 2; im++) {
                uint32_t ro = (a_row + im * 16) * 128 + (((ks * 2 + a_cq) ^ t7) << 4);
                LDSM4(af[im][0], af[im][1], af[im][2], af[im][3], st + ro);
            }
            uint32_t bf[8][2];
            #pragma unroll
            for (int jj = 0; jj < 4; jj++) {
                uint32_t ro = (b_row + jj * 16) * 128 + (((ks * 2 + b_cq) ^ t7) << 4);
                LDSM4(bf[2*jj][0], bf[2*jj][1], bf[2*jj+1][0], bf[2*jj+1][1],
                      st + TILE_B + ro);
            }
            #pragma unroll
            for (int im = 0; im < 2; im++)
                #pragma unroll
                for (int jt = 0; jt < 8; jt++)
                    MMA_F16(acc[im][jt], af[im], bf[jt]);
        }

        buf  = (buf == STG - 1) ? 0 : buf + 1;
        lbuf = (lbuf == STG - 1) ? 0 : lbuf + 1;
    }

    #pragma unroll
    for (int im = 0; im < 2; im++) {
        int r0 = bm + wm * 32 + im * 16 + (lane >> 2);
        #pragma unroll
        for (int jt = 0; jt < 8; jt++) {
            int c = bn + wn * 64 + jt * 8 + (lane & 3) * 2;
            *(float2*)&C[(size_t)r0 * D_ + c]       = make_float2(acc[im][jt][0], acc[im][jt][1]);
            *(float2*)&C[(size_t)(r0 + 8) * D_ + c] = make_float2(acc[im][jt][2], acc[im][jt][3]);
        }
    }
}

// ============================ launch ============================
extern "C" void kernel_launch(void* const* d_in, const int* in_sizes, int n_in,
                              void* d_out, int out_size) {
    const float* x           = (const float*)d_in[0];
    const float* q           = (const float*)d_in[1];
    const float* k           = (const float*)d_in[2];
    const float* log_decay   = (const float*)d_in[3];
    const float* norm_weight = (const float*)d_in[4];
    const float* o_w         = (const float*)d_in[5];
    float* out = (float*)d_out;

    cudaFuncSetAttribute(k_scan_fused, cudaFuncAttributeMaxDynamicSharedMemorySize, SNORM_SMEM);
    k_scan_fused<<<B_ * NCH_, 1024, SNORM_SMEM>>>(x, norm_weight, q, k, log_decay, o_w);

    cudaFuncSetAttribute(k_gemm_mma, cudaFuncAttributeMaxDynamicSharedMemorySize,
                         SMEM_GEMM_TOTAL);
    dim3 grid(D_ / GN, M_ / GM);
    k_gemm_mma<<<grid, 256, SMEM_GEMM_TOTAL>>>(out);
}